// round 1
// baseline (speedup 1.0000x reference)
#include <cuda_runtime.h>
#include <cstdint>

#define BATCH 64
#define NSEQ  2048
#define CDIM  128
#define HP    64
#define WP    32
#define HG    32   // HP / POOL
#define D_SCALE 0.08838834764831845f  // 1/sqrt(128)

// Scratch: Q,K,V in [B, C, N] (spatial-major) layout. V plane is overwritten
// with the attention output by attn_kernel (each CTA exclusively owns its plane,
// and proj_kernel fully rewrites it on every graph replay -> deterministic).
__device__ float g_QT[(size_t)BATCH * CDIM * NSEQ];
__device__ float g_KT[(size_t)BATCH * CDIM * NSEQ];
__device__ float g_VT[(size_t)BATCH * CDIM * NSEQ];

// ---------------------------------------------------------------------------
// Kernel 1: projection GEMM. Out[m, j] = sigmoid( sum_c X[m,c] * W[j,c] + b[j] )
// written transposed into scratch[b][j][n], n = m % 2048.
// Tile: 128 rows (m) x 128 cols (j), K = 128 fully staged in smem.
// blockIdx.y in {0,1,2} selects Q/K/V.
// ---------------------------------------------------------------------------
__global__ __launch_bounds__(256) void proj_kernel(
    const float* __restrict__ X,
    const float* __restrict__ Wq, const float* __restrict__ bq,
    const float* __restrict__ Wk, const float* __restrict__ bk,
    const float* __restrict__ Wv, const float* __restrict__ bv)
{
    extern __shared__ float sm[];
    float* As = sm;              // [k][m], stride 132
    float* Bs = sm + 128 * 132;  // [k][j], stride 132

    const int which = blockIdx.y;
    const float* W    = (which == 0) ? Wq : (which == 1) ? Wk : Wv;
    const float* bias = (which == 0) ? bq : (which == 1) ? bk : bv;
    float* OutT       = (which == 0) ? g_QT : (which == 1) ? g_KT : g_VT;

    const int t  = threadIdx.x;
    const int M0 = blockIdx.x * 128;

    // Load X tile and W (transposed into k-major smem).
    {
        const int r  = t >> 5;          // 0..7
        const int c4 = (t & 31) << 2;   // 0..124
        #pragma unroll
        for (int it = 0; it < 16; ++it) {
            const int row = it * 8 + r;
            float4 xv = *(const float4*)(X + (size_t)(M0 + row) * CDIM + c4);
            As[(c4 + 0) * 132 + row] = xv.x;
            As[(c4 + 1) * 132 + row] = xv.y;
            As[(c4 + 2) * 132 + row] = xv.z;
            As[(c4 + 3) * 132 + row] = xv.w;
            float4 wv = *(const float4*)(W + (size_t)row * CDIM + c4);
            Bs[(c4 + 0) * 132 + row] = wv.x;
            Bs[(c4 + 1) * 132 + row] = wv.y;
            Bs[(c4 + 2) * 132 + row] = wv.z;
            Bs[(c4 + 3) * 132 + row] = wv.w;
        }
    }
    __syncthreads();

    const int tx = t & 15;   // m micro-tile (so stores along n are coalesced)
    const int ty = t >> 4;   // j micro-tile

    float acc[8][8];
    #pragma unroll
    for (int i = 0; i < 8; ++i)
        #pragma unroll
        for (int j = 0; j < 8; ++j)
            acc[i][j] = 0.0f;

    #pragma unroll 8
    for (int k = 0; k < 128; ++k) {
        float4 a0 = *(const float4*)(As + k * 132 + tx * 8);
        float4 a1 = *(const float4*)(As + k * 132 + tx * 8 + 4);
        float4 b0 = *(const float4*)(Bs + k * 132 + ty * 8);
        float4 b1 = *(const float4*)(Bs + k * 132 + ty * 8 + 4);
        float a[8] = {a0.x, a0.y, a0.z, a0.w, a1.x, a1.y, a1.z, a1.w};
        float b[8] = {b0.x, b0.y, b0.z, b0.w, b1.x, b1.y, b1.z, b1.w};
        #pragma unroll
        for (int i = 0; i < 8; ++i)
            #pragma unroll
            for (int j = 0; j < 8; ++j)
                acc[i][j] = fmaf(a[i], b[j], acc[i][j]);
    }

    const int bidx = M0 >> 11;                 // 2048 rows per batch, 128 | 2048
    const int n0   = (M0 & 2047) + tx * 8;

    #pragma unroll
    for (int j = 0; j < 8; ++j) {
        const int jj = ty * 8 + j;
        const float bj = __ldg(bias + jj);
        float v[8];
        #pragma unroll
        for (int i = 0; i < 8; ++i) {
            float x = acc[i][j] + bj;
            v[i] = 1.0f / (1.0f + __expf(-x));
        }
        float* dst = OutT + ((size_t)bidx * CDIM + jj) * NSEQ + n0;
        *(float4*)(dst)     = make_float4(v[0], v[1], v[2], v[3]);
        *(float4*)(dst + 4) = make_float4(v[4], v[5], v[6], v[7]);
    }
}

// ---------------------------------------------------------------------------
// Kernel 2: per-(b,c) dual-softmax attention on a [64,32] plane.
// 256 threads (8 warps). K is staged transposed so per-lane dot products are
// bank-conflict free; warp-grouped rows share the per-lane K loads.
// ---------------------------------------------------------------------------
__global__ __launch_bounds__(256) void attn_kernel()
{
    const int bc = blockIdx.x;                      // b*128 + c
    const float* Qp = g_QT + (size_t)bc * NSEQ;
    const float* Kp = g_KT + (size_t)bc * NSEQ;
    const float* Vp = g_VT + (size_t)bc * NSEQ;
    float* Op = g_VT + (size_t)bc * NSEQ;           // overwrite V plane

    __shared__ float Qs[HP * WP];     // [h][w]
    __shared__ float Vs[HP * WP];     // [h][w]
    __shared__ float KTs[WP * 65];    // [w][h], padded
    __shared__ float kTs[WP * 33];    // [w][g], pooled K, padded
    __shared__ float qs[HG * WP];     // [g][w], pooled Q
    __shared__ float Kqvs[HG * WP];   // [g][w]
    __shared__ float buf[8][264];     // per-warp softmax rows

    const int t    = threadIdx.x;
    const int warp = t >> 5;
    const int lane = t & 31;

    // Load Q, V linear; K transposed into KTs.
    #pragma unroll
    for (int i = 0; i < 2; ++i) {
        int idx = (t + i * 256) * 4;                // 0..8188 step 4 (floats)
        float4 qv = *(const float4*)(Qp + idx);
        float4 vv = *(const float4*)(Vp + idx);
        float4 kv = *(const float4*)(Kp + idx);
        *(float4*)(Qs + idx) = qv;
        *(float4*)(Vs + idx) = vv;
        int h = idx >> 5, w = idx & 31;
        KTs[(w + 0) * 65 + h] = kv.x;
        KTs[(w + 1) * 65 + h] = kv.y;
        KTs[(w + 2) * 65 + h] = kv.z;
        KTs[(w + 3) * 65 + h] = kv.w;
    }
    __syncthreads();

    // Pool over h (mean of pairs): q = pool(Q), k = pool(K) stored transposed.
    #pragma unroll
    for (int i = 0; i < 4; ++i) {
        int idx = t + i * 256;          // 0..1023
        int g = idx >> 5, w = idx & 31;
        qs[g * 32 + w]  = 0.5f * (Qs[(2 * g) * 32 + w] + Qs[(2 * g + 1) * 32 + w]);
        kTs[w * 33 + g] = 0.5f * (KTs[w * 65 + 2 * g] + KTs[w * 65 + 2 * g + 1]);
    }
    __syncthreads();

    // ---- Kq = softmax_h(scale * q @ K^T), Kqv = Kq @ V : 32 g-rows, 4/warp ----
    {
        const int g0 = warp * 4;
        float s0[4] = {0, 0, 0, 0}, s1[4] = {0, 0, 0, 0};
        #pragma unroll
        for (int w = 0; w < 32; ++w) {
            float k0 = KTs[w * 65 + lane];
            float k1 = KTs[w * 65 + 32 + lane];
            #pragma unroll
            for (int gi = 0; gi < 4; ++gi) {
                float qv = qs[(g0 + gi) * 32 + w];
                s0[gi] = fmaf(qv, k0, s0[gi]);
                s1[gi] = fmaf(qv, k1, s1[gi]);
            }
        }
        #pragma unroll
        for (int gi = 0; gi < 4; ++gi) {
            float a = s0[gi] * D_SCALE, b = s1[gi] * D_SCALE;
            float m = fmaxf(a, b);
            #pragma unroll
            for (int o = 16; o; o >>= 1) m = fmaxf(m, __shfl_xor_sync(0xffffffffu, m, o));
            float e0 = __expf(a - m), e1 = __expf(b - m);
            float sum = e0 + e1;
            #pragma unroll
            for (int o = 16; o; o >>= 1) sum += __shfl_xor_sync(0xffffffffu, sum, o);
            float r = __frcp_rn(sum);
            buf[warp][gi * 66 + lane]      = e0 * r;
            buf[warp][gi * 66 + 32 + lane] = e1 * r;
        }
        __syncwarp();
        // Kqv[g][w] = sum_h Kq[g][h] * V[h][w];  lane -> (gi, 4 w's)
        const int gi = lane >> 3;
        const int w4 = (lane & 7) << 2;
        float4 acc = {0, 0, 0, 0};
        #pragma unroll 8
        for (int h = 0; h < 64; ++h) {
            float p  = buf[warp][gi * 66 + h];
            float4 v = *(const float4*)(Vs + h * 32 + w4);
            acc.x = fmaf(p, v.x, acc.x);
            acc.y = fmaf(p, v.y, acc.y);
            acc.z = fmaf(p, v.z, acc.z);
            acc.w = fmaf(p, v.w, acc.w);
        }
        *(float4*)(Kqvs + (g0 + gi) * 32 + w4) = acc;
    }
    __syncthreads();

    // ---- Qk = softmax_g(scale * Q @ k^T), out = Qk @ Kqv : 64 h-rows, 8/warp ----
    {
        const int h0 = warp * 8;
        float s[8] = {0, 0, 0, 0, 0, 0, 0, 0};
        #pragma unroll
        for (int w = 0; w < 32; ++w) {
            float kt = kTs[w * 33 + lane];
            #pragma unroll
            for (int hi = 0; hi < 8; ++hi)
                s[hi] = fmaf(Qs[(h0 + hi) * 32 + w], kt, s[hi]);
        }
        #pragma unroll
        for (int hi = 0; hi < 8; ++hi) {
            float a = s[hi] * D_SCALE;
            float m = a;
            #pragma unroll
            for (int o = 16; o; o >>= 1) m = fmaxf(m, __shfl_xor_sync(0xffffffffu, m, o));
            float e = __expf(a - m);
            float sum = e;
            #pragma unroll
            for (int o = 16; o; o >>= 1) sum += __shfl_xor_sync(0xffffffffu, sum, o);
            buf[warp][hi * 33 + lane] = e * __frcp_rn(sum);
        }
        __syncwarp();
        // out[h][w] = sum_g Qk[h][g] * Kqv[g][w];  lane -> (hi, 8 w's)
        const int hi = lane >> 2;
        const int w8 = (lane & 3) << 3;
        float4 acc0 = {0, 0, 0, 0}, acc1 = {0, 0, 0, 0};
        #pragma unroll 8
        for (int g = 0; g < 32; ++g) {
            float p   = buf[warp][hi * 33 + g];
            float4 v0 = *(const float4*)(Kqvs + g * 32 + w8);
            float4 v1 = *(const float4*)(Kqvs + g * 32 + w8 + 4);
            acc0.x = fmaf(p, v0.x, acc0.x);
            acc0.y = fmaf(p, v0.y, acc0.y);
            acc0.z = fmaf(p, v0.z, acc0.z);
            acc0.w = fmaf(p, v0.w, acc0.w);
            acc1.x = fmaf(p, v1.x, acc1.x);
            acc1.y = fmaf(p, v1.y, acc1.y);
            acc1.z = fmaf(p, v1.z, acc1.z);
            acc1.w = fmaf(p, v1.w, acc1.w);
        }
        float* dst = Op + (h0 + hi) * 32 + w8;
        *(float4*)(dst)     = acc0;
        *(float4*)(dst + 4) = acc1;
    }
}

// ---------------------------------------------------------------------------
// Kernel 3: [B, C, N] -> [B, N, C] transpose (output epilogue).
// ---------------------------------------------------------------------------
__global__ __launch_bounds__(256) void transpose_kernel(float* __restrict__ out)
{
    __shared__ float tile[32][33];
    const int b  = blockIdx.z;
    const int c0 = blockIdx.y * 32;
    const int n0 = blockIdx.x * 32;
    const int tx = threadIdx.x;   // 0..31
    const int ty = threadIdx.y;   // 0..7

    const float* src = g_VT + (size_t)b * CDIM * NSEQ;
    #pragma unroll
    for (int i = 0; i < 32; i += 8)
        tile[ty + i][tx] = src[(size_t)(c0 + ty + i) * NSEQ + n0 + tx];
    __syncthreads();
    #pragma unroll
    for (int i = 0; i < 32; i += 8)
        out[((size_t)b * NSEQ + n0 + ty + i) * CDIM + c0 + tx] = tile[tx][ty + i];
}

// ---------------------------------------------------------------------------
extern "C" void kernel_launch(void* const* d_in, const int* in_sizes, int n_in,
                              void* d_out, int out_size)
{
    (void)in_sizes; (void)n_in; (void)out_size;
    const float* X  = (const float*)d_in[0];
    const float* Wq = (const float*)d_in[1];
    const float* bq = (const float*)d_in[2];
    const float* Wk = (const float*)d_in[3];
    const float* bk = (const float*)d_in[4];
    const float* Wv = (const float*)d_in[5];
    const float* bv = (const float*)d_in[6];
    float* out = (float*)d_out;

    const size_t proj_smem = (size_t)128 * 132 * 2 * sizeof(float);  // 135168 B
    cudaFuncSetAttribute(proj_kernel, cudaFuncAttributeMaxDynamicSharedMemorySize,
                         (int)proj_smem);

    proj_kernel<<<dim3(1024, 3, 1), 256, proj_smem>>>(X, Wq, bq, Wk, bk, Wv, bv);
    attn_kernel<<<dim3(BATCH * CDIM, 1, 1), 256>>>();
    transpose_kernel<<<dim3(NSEQ / 32, CDIM / 32, BATCH), dim3(32, 8, 1)>>>(out);
}

// round 2
// speedup vs baseline: 1.1322x; 1.1322x over previous
#include <cuda_runtime.h>
#include <cstdint>

#define BATCH 64
#define NSEQ  2048
#define CDIM  128
#define HP    64
#define WP    32
#define HG    32   // HP / POOL
#define D_SCALE 0.08838834764831845f  // 1/sqrt(128)

// Scratch: Q,K,V in [B, C, N] (spatial-major) layout. V plane is overwritten
// with the attention output by attn_kernel (each CTA exclusively owns its plane,
// and proj writes it fully on every graph replay -> deterministic).
__device__ float g_QT[(size_t)BATCH * CDIM * NSEQ];
__device__ float g_KT[(size_t)BATCH * CDIM * NSEQ];
__device__ float g_VT[(size_t)BATCH * CDIM * NSEQ];

#define SSTR 132   // smem row stride (floats): bank = (4*row + col) & 31 -> conflict-free

__device__ __forceinline__ uint32_t f2tf32(float x) {
    uint32_t r;
    asm("cvt.rna.tf32.f32 %0, %1;" : "=r"(r) : "f"(x));
    return r;
}

__device__ __forceinline__ void mma_tf32(float& d0, float& d1, float& d2, float& d3,
                                         uint32_t a0, uint32_t a1, uint32_t a2, uint32_t a3,
                                         uint32_t b0, uint32_t b1) {
    asm volatile(
        "mma.sync.aligned.m16n8k8.row.col.f32.tf32.tf32.f32 "
        "{%0,%1,%2,%3}, {%4,%5,%6,%7}, {%8,%9}, {%0,%1,%2,%3};"
        : "+f"(d0), "+f"(d1), "+f"(d2), "+f"(d3)
        : "r"(a0), "r"(a1), "r"(a2), "r"(a3), "r"(b0), "r"(b1));
}

// ---------------------------------------------------------------------------
// Kernel 1: projection GEMMs on tensor cores (3xTF32 split for fp32 accuracy).
// One CTA = one 128-row M-tile of X, computing Q, K, V sequentially.
// Out[m,j] = sigmoid(sum_c X[m,c] W[j,c] + b[j]) stored transposed: OutT[b][j][n].
// ---------------------------------------------------------------------------
__global__ __launch_bounds__(256) void proj_mma_kernel(
    const float* __restrict__ X,
    const float* __restrict__ Wq, const float* __restrict__ bq,
    const float* __restrict__ Wk, const float* __restrict__ bk,
    const float* __restrict__ Wv, const float* __restrict__ bv)
{
    extern __shared__ float sm[];
    float* Xs  = sm;               // [m][c]  128 x SSTR (fp32)
    float* Whi = sm + 128 * SSTR;  // [j][c]  128 x SSTR (tf32 bits as float)
    float* Wlo = Whi + 128 * SSTR; // [j][c]  128 x SSTR

    const int t    = threadIdx.x;
    const int warp = t >> 5;
    const int lane = t & 31;
    const int M0   = blockIdx.x * 128;
    const int bidx = M0 >> 11;         // batch index (128 | 2048)
    const int n0   = M0 & 2047;        // seq offset within batch

    // ---- Stage X tile [128 x 128] into smem (fp32) ----
    {
        const int r  = t >> 5;          // 0..7
        const int c4 = (t & 31) << 2;   // 0..124
        #pragma unroll
        for (int it = 0; it < 16; ++it) {
            const int row = it * 8 + r;
            float4 xv = *(const float4*)(X + (size_t)(M0 + row) * CDIM + c4);
            *(float4*)(Xs + row * SSTR + c4) = xv;
        }
    }

    const int g   = lane >> 2;   // group id 0..7
    const int tid = lane & 3;    // thread-in-group 0..3

    #pragma unroll 1
    for (int p = 0; p < 3; ++p) {
        const float* W    = (p == 0) ? Wq : (p == 1) ? Wk : Wv;
        const float* bias = (p == 0) ? bq : (p == 1) ? bk : bv;
        float* OutT       = (p == 0) ? g_QT : (p == 1) ? g_KT : g_VT;

        __syncthreads();   // previous iter's epilogue done reading Whi / Xs stable

        // ---- Stage W_p, split into tf32 hi/lo ----
        {
            const int r  = t >> 5;
            const int c4 = (t & 31) << 2;
            #pragma unroll
            for (int it = 0; it < 16; ++it) {
                const int row = it * 8 + r;
                float4 wv = *(const float4*)(W + (size_t)row * CDIM + c4);
                float w[4] = {wv.x, wv.y, wv.z, wv.w};
                float4 hi, lo;
                float* hp = &hi.x; float* lp = &lo.x;
                #pragma unroll
                for (int q = 0; q < 4; ++q) {
                    uint32_t h = f2tf32(w[q]);
                    hp[q] = __uint_as_float(h);
                    lp[q] = __uint_as_float(f2tf32(w[q] - hp[q]));
                }
                *(float4*)(Whi + row * SSTR + c4) = hi;
                *(float4*)(Wlo + row * SSTR + c4) = lo;
            }
        }
        __syncthreads();

        // ---- MMA mainloop: warp owns m-rows [16*warp, 16*warp+16), all 128 j ----
        float acc[16][4];
        #pragma unroll
        for (int nt = 0; nt < 16; ++nt)
            #pragma unroll
            for (int q = 0; q < 4; ++q) acc[nt][q] = 0.0f;

        const int mbase = warp * 16;
        #pragma unroll
        for (int ks = 0; ks < 16; ++ks) {
            const int c0 = tid + ks * 8;
            // A fragments (m16 x k8), convert fp32 -> tf32 hi/lo on the fly
            float ar0 = Xs[(mbase + g) * SSTR + c0];
            float ar1 = Xs[(mbase + g + 8) * SSTR + c0];
            float ar2 = Xs[(mbase + g) * SSTR + c0 + 4];
            float ar3 = Xs[(mbase + g + 8) * SSTR + c0 + 4];
            uint32_t ah0 = f2tf32(ar0), ah1 = f2tf32(ar1);
            uint32_t ah2 = f2tf32(ar2), ah3 = f2tf32(ar3);
            uint32_t al0 = f2tf32(ar0 - __uint_as_float(ah0));
            uint32_t al1 = f2tf32(ar1 - __uint_as_float(ah1));
            uint32_t al2 = f2tf32(ar2 - __uint_as_float(ah2));
            uint32_t al3 = f2tf32(ar3 - __uint_as_float(ah3));

            #pragma unroll
            for (int nt = 0; nt < 16; ++nt) {
                const int j = g + nt * 8;
                uint32_t bh0 = __float_as_uint(Whi[j * SSTR + c0]);
                uint32_t bh1 = __float_as_uint(Whi[j * SSTR + c0 + 4]);
                uint32_t bl0 = __float_as_uint(Wlo[j * SSTR + c0]);
                uint32_t bl1 = __float_as_uint(Wlo[j * SSTR + c0 + 4]);
                mma_tf32(acc[nt][0], acc[nt][1], acc[nt][2], acc[nt][3],
                         ah0, ah1, ah2, ah3, bh0, bh1);
                mma_tf32(acc[nt][0], acc[nt][1], acc[nt][2], acc[nt][3],
                         al0, al1, al2, al3, bh0, bh1);
                mma_tf32(acc[nt][0], acc[nt][1], acc[nt][2], acc[nt][3],
                         ah0, ah1, ah2, ah3, bl0, bl1);
            }
        }

        __syncthreads();   // all warps done reading Whi/Wlo -> reuse Whi as transpose buf

        // ---- Epilogue: bias + sigmoid, transpose to [j][m] via smem ----
        float* T = Whi;
        #pragma unroll
        for (int nt = 0; nt < 16; ++nt) {
            const int j0 = 2 * tid + nt * 8;
            const float b0v = __ldg(bias + j0);
            const float b1v = __ldg(bias + j0 + 1);
            float v0 = acc[nt][0] + b0v;
            float v1 = acc[nt][1] + b1v;
            float v2 = acc[nt][2] + b0v;
            float v3 = acc[nt][3] + b1v;
            v0 = 1.0f / (1.0f + __expf(-v0));
            v1 = 1.0f / (1.0f + __expf(-v1));
            v2 = 1.0f / (1.0f + __expf(-v2));
            v3 = 1.0f / (1.0f + __expf(-v3));
            T[j0 * SSTR + mbase + g]           = v0;
            T[(j0 + 1) * SSTR + mbase + g]     = v1;
            T[j0 * SSTR + mbase + g + 8]       = v2;
            T[(j0 + 1) * SSTR + mbase + g + 8] = v3;
        }
        __syncthreads();

        // ---- Coalesced float4 store: OutT[bidx][j][n0 + m] ----
        #pragma unroll
        for (int it = 0; it < 16; ++it) {
            const int idx = t + it * 256;       // 0..4095
            const int j   = idx >> 5;
            const int m4  = (idx & 31) << 2;
            float4 v = *(const float4*)(T + j * SSTR + m4);
            *(float4*)(OutT + ((size_t)bidx * CDIM + j) * NSEQ + n0 + m4) = v;
        }
    }
}

// ---------------------------------------------------------------------------
// Kernel 2: per-(b,c) dual-softmax attention on a [64,32] plane.
// ---------------------------------------------------------------------------
__global__ __launch_bounds__(256) void attn_kernel()
{
    const int bc = blockIdx.x;                      // b*128 + c
    const float* Qp = g_QT + (size_t)bc * NSEQ;
    const float* Kp = g_KT + (size_t)bc * NSEQ;
    const float* Vp = g_VT + (size_t)bc * NSEQ;
    float* Op = g_VT + (size_t)bc * NSEQ;           // overwrite V plane

    __shared__ float Qs[HP * WP];     // [h][w]
    __shared__ float Vs[HP * WP];     // [h][w]
    __shared__ float KTs[WP * 65];    // [w][h], padded
    __shared__ float kTs[WP * 33];    // [w][g], pooled K, padded
    __shared__ float qs[HG * WP];     // [g][w], pooled Q
    __shared__ float Kqvs[HG * WP];   // [g][w]
    __shared__ float buf[8][264];     // per-warp softmax rows

    const int t    = threadIdx.x;
    const int warp = t >> 5;
    const int lane = t & 31;

    #pragma unroll
    for (int i = 0; i < 2; ++i) {
        int idx = (t + i * 256) * 4;
        float4 qv = *(const float4*)(Qp + idx);
        float4 vv = *(const float4*)(Vp + idx);
        float4 kv = *(const float4*)(Kp + idx);
        *(float4*)(Qs + idx) = qv;
        *(float4*)(Vs + idx) = vv;
        int h = idx >> 5, w = idx & 31;
        KTs[(w + 0) * 65 + h] = kv.x;
        KTs[(w + 1) * 65 + h] = kv.y;
        KTs[(w + 2) * 65 + h] = kv.z;
        KTs[(w + 3) * 65 + h] = kv.w;
    }
    __syncthreads();

    #pragma unroll
    for (int i = 0; i < 4; ++i) {
        int idx = t + i * 256;
        int g = idx >> 5, w = idx & 31;
        qs[g * 32 + w]  = 0.5f * (Qs[(2 * g) * 32 + w] + Qs[(2 * g + 1) * 32 + w]);
        kTs[w * 33 + g] = 0.5f * (KTs[w * 65 + 2 * g] + KTs[w * 65 + 2 * g + 1]);
    }
    __syncthreads();

    // ---- Kq = softmax_h(scale * q @ K^T), Kqv = Kq @ V ----
    {
        const int g0 = warp * 4;
        float s0[4] = {0, 0, 0, 0}, s1[4] = {0, 0, 0, 0};
        #pragma unroll
        for (int w = 0; w < 32; ++w) {
            float k0 = KTs[w * 65 + lane];
            float k1 = KTs[w * 65 + 32 + lane];
            #pragma unroll
            for (int gi = 0; gi < 4; ++gi) {
                float qv = qs[(g0 + gi) * 32 + w];
                s0[gi] = fmaf(qv, k0, s0[gi]);
                s1[gi] = fmaf(qv, k1, s1[gi]);
            }
        }
        #pragma unroll
        for (int gi = 0; gi < 4; ++gi) {
            float a = s0[gi] * D_SCALE, b = s1[gi] * D_SCALE;
            float m = fmaxf(a, b);
            #pragma unroll
            for (int o = 16; o; o >>= 1) m = fmaxf(m, __shfl_xor_sync(0xffffffffu, m, o));
            float e0 = __expf(a - m), e1 = __expf(b - m);
            float sum = e0 + e1;
            #pragma unroll
            for (int o = 16; o; o >>= 1) sum += __shfl_xor_sync(0xffffffffu, sum, o);
            float r = __frcp_rn(sum);
            buf[warp][gi * 66 + lane]      = e0 * r;
            buf[warp][gi * 66 + 32 + lane] = e1 * r;
        }
        __syncwarp();
        const int gi = lane >> 3;
        const int w4 = (lane & 7) << 2;
        float4 acc = {0, 0, 0, 0};
        #pragma unroll 8
        for (int h = 0; h < 64; ++h) {
            float p  = buf[warp][gi * 66 + h];
            float4 v = *(const float4*)(Vs + h * 32 + w4);
            acc.x = fmaf(p, v.x, acc.x);
            acc.y = fmaf(p, v.y, acc.y);
            acc.z = fmaf(p, v.z, acc.z);
            acc.w = fmaf(p, v.w, acc.w);
        }
        *(float4*)(Kqvs + (g0 + gi) * 32 + w4) = acc;
    }
    __syncthreads();

    // ---- Qk = softmax_g(scale * Q @ k^T), out = Qk @ Kqv ----
    {
        const int h0 = warp * 8;
        float s[8] = {0, 0, 0, 0, 0, 0, 0, 0};
        #pragma unroll
        for (int w = 0; w < 32; ++w) {
            float kt = kTs[w * 33 + lane];
            #pragma unroll
            for (int hi = 0; hi < 8; ++hi)
                s[hi] = fmaf(Qs[(h0 + hi) * 32 + w], kt, s[hi]);
        }
        #pragma unroll
        for (int hi = 0; hi < 8; ++hi) {
            float a = s[hi] * D_SCALE;
            float m = a;
            #pragma unroll
            for (int o = 16; o; o >>= 1) m = fmaxf(m, __shfl_xor_sync(0xffffffffu, m, o));
            float e = __expf(a - m);
            float sum = e;
            #pragma unroll
            for (int o = 16; o; o >>= 1) sum += __shfl_xor_sync(0xffffffffu, sum, o);
            buf[warp][hi * 33 + lane] = e * __frcp_rn(sum);
        }
        __syncwarp();
        const int hi = lane >> 2;
        const int w8 = (lane & 3) << 3;
        float4 acc0 = {0, 0, 0, 0}, acc1 = {0, 0, 0, 0};
        #pragma unroll 8
        for (int g = 0; g < 32; ++g) {
            float p   = buf[warp][hi * 33 + g];
            float4 v0 = *(const float4*)(Kqvs + g * 32 + w8);
            float4 v1 = *(const float4*)(Kqvs + g * 32 + w8 + 4);
            acc0.x = fmaf(p, v0.x, acc0.x);
            acc0.y = fmaf(p, v0.y, acc0.y);
            acc0.z = fmaf(p, v0.z, acc0.z);
            acc0.w = fmaf(p, v0.w, acc0.w);
            acc1.x = fmaf(p, v1.x, acc1.x);
            acc1.y = fmaf(p, v1.y, acc1.y);
            acc1.z = fmaf(p, v1.z, acc1.z);
            acc1.w = fmaf(p, v1.w, acc1.w);
        }
        float* dst = Op + (h0 + hi) * 32 + w8;
        *(float4*)(dst)     = acc0;
        *(float4*)(dst + 4) = acc1;
    }
}

// ---------------------------------------------------------------------------
// Kernel 3: [B, C, N] -> [B, N, C] transpose (output epilogue).
// ---------------------------------------------------------------------------
__global__ __launch_bounds__(256) void transpose_kernel(float* __restrict__ out)
{
    __shared__ float tile[32][33];
    const int b  = blockIdx.z;
    const int c0 = blockIdx.y * 32;
    const int n0 = blockIdx.x * 32;
    const int tx = threadIdx.x;
    const int ty = threadIdx.y;

    const float* src = g_VT + (size_t)b * CDIM * NSEQ;
    #pragma unroll
    for (int i = 0; i < 32; i += 8)
        tile[ty + i][tx] = src[(size_t)(c0 + ty + i) * NSEQ + n0 + tx];
    __syncthreads();
    #pragma unroll
    for (int i = 0; i < 32; i += 8)
        out[((size_t)b * NSEQ + n0 + ty + i) * CDIM + c0 + tx] = tile[tx][ty + i];
}

// ---------------------------------------------------------------------------
extern "C" void kernel_launch(void* const* d_in, const int* in_sizes, int n_in,
                              void* d_out, int out_size)
{
    (void)in_sizes; (void)n_in; (void)out_size;
    const float* X  = (const float*)d_in[0];
    const float* Wq = (const float*)d_in[1];
    const float* bq = (const float*)d_in[2];
    const float* Wk = (const float*)d_in[3];
    const float* bk = (const float*)d_in[4];
    const float* Wv = (const float*)d_in[5];
    const float* bv = (const float*)d_in[6];
    float* out = (float*)d_out;

    const size_t proj_smem = (size_t)3 * 128 * SSTR * sizeof(float);  // 202752 B
    cudaFuncSetAttribute(proj_mma_kernel, cudaFuncAttributeMaxDynamicSharedMemorySize,
                         (int)proj_smem);

    proj_mma_kernel<<<dim3(1024, 1, 1), 256, proj_smem>>>(X, Wq, bq, Wk, bk, Wv, bv);
    attn_kernel<<<dim3(BATCH * CDIM, 1, 1), 256>>>();
    transpose_kernel<<<dim3(NSEQ / 32, CDIM / 32, BATCH), dim3(32, 8, 1)>>>(out);
}

// round 3
// speedup vs baseline: 1.3886x; 1.2264x over previous
#include <cuda_runtime.h>
#include <cstdint>

#define BATCH 64
#define NSEQ  2048
#define CDIM  128
#define HP    64
#define WP    32
#define HG    32   // HP / POOL
#define D_SCALE 0.08838834764831845f  // 1/sqrt(128)

// Scratch: Q,K,V in [B, C, N] (spatial-major) layout. V plane is overwritten
// with the attention output by attn_kernel (each CTA exclusively owns its plane,
// and proj writes it fully on every graph replay -> deterministic).
__device__ float g_QT[(size_t)BATCH * CDIM * NSEQ];
__device__ float g_KT[(size_t)BATCH * CDIM * NSEQ];
__device__ float g_VT[(size_t)BATCH * CDIM * NSEQ];

#define SSTR 132   // smem row stride (floats) for X / transpose buffer

__device__ __forceinline__ uint32_t f2tf32(float x) {
    uint32_t r;
    asm("cvt.rna.tf32.f32 %0, %1;" : "=r"(r) : "f"(x));
    return r;
}

__device__ __forceinline__ void mma_tf32(float& d0, float& d1, float& d2, float& d3,
                                         uint32_t a0, uint32_t a1, uint32_t a2, uint32_t a3,
                                         uint32_t b0, uint32_t b1) {
    asm volatile(
        "mma.sync.aligned.m16n8k8.row.col.f32.tf32.tf32.f32 "
        "{%0,%1,%2,%3}, {%4,%5,%6,%7}, {%8,%9}, {%0,%1,%2,%3};"
        : "+f"(d0), "+f"(d1), "+f"(d2), "+f"(d3)
        : "r"(a0), "r"(a1), "r"(a2), "r"(a3), "r"(b0), "r"(b1));
}

// ---------------------------------------------------------------------------
// Kernel 1: projection GEMMs on tensor cores (3xTF32 split for fp32 accuracy).
// 512 threads = 16 warps: warp = (mgroup 0..7) x (nhalf 0..1).
// W is staged in smem in MMA-fragment-packed order (float2 per lane), with a
// lane^ks swizzle for conflict-free stage AND read.
// Out[m,j] = sigmoid(sum_c X[m,c] W[j,c] + b[j]), stored transposed OutT[b][j][n].
// ---------------------------------------------------------------------------
__global__ __launch_bounds__(512) void proj_mma_kernel(
    const float* __restrict__ X,
    const float* __restrict__ Wq, const float* __restrict__ bq,
    const float* __restrict__ Wk, const float* __restrict__ bk,
    const float* __restrict__ Wv, const float* __restrict__ bv)
{
    extern __shared__ float sm[];
    float* Xs  = sm;                     // [m][c] 128 x SSTR fp32        (67.6 KB)
    float* Whi = sm + 128 * SSTR;        // packed frag: [nt][ks][lane]x2 (64 KB)
    float* Wlo = Whi + 16 * 16 * 32 * 2; // packed frag: [nt][ks][lane]x2 (64 KB)
    // epilogue transpose buffer T reuses Whi..Wlo region (needs 67.6 KB)

    const int t    = threadIdx.x;
    const int warp = t >> 5;
    const int lane = t & 31;
    const int M0   = blockIdx.x * 128;
    const int bidx = M0 >> 11;          // batch index (128 | 2048)
    const int n0   = M0 & 2047;         // seq offset within batch

    // ---- Stage X tile [128 x 128] fp32 ----
    {
        const int r  = t >> 5;           // 0..15
        const int c4 = (t & 31) << 2;    // 0..124
        #pragma unroll
        for (int it = 0; it < 8; ++it) {
            const int row = it * 16 + r;
            float4 xv = *(const float4*)(X + (size_t)(M0 + row) * CDIM + c4);
            *(float4*)(Xs + row * SSTR + c4) = xv;
        }
    }

    const int g      = lane >> 2;    // 0..7
    const int tid    = lane & 3;     // 0..3
    const int mgroup = warp & 7;
    const int nhalf  = warp >> 3;
    const int mbase  = mgroup * 16;

    #pragma unroll 1
    for (int p = 0; p < 3; ++p) {
        const float* W    = (p == 0) ? Wq : (p == 1) ? Wk : Wv;
        const float* bias = (p == 0) ? bq : (p == 1) ? bk : bv;
        float* OutT       = (p == 0) ? g_QT : (p == 1) ? g_KT : g_VT;

        __syncthreads();   // prev epilogue done with Whi region; Xs stable

        // ---- Stage W in fragment-packed tf32 hi/lo ----
        // value W[j][c] -> buf[((nt*16+ks)*32 + ((g*4+q)^ks))*2 + slot]
        //   nt=j>>3, g=j&7, ks=c>>3, q=c&3, slot=(c>>2)&1
        {
            const int r  = t >> 5;            // 0..15 (row group)
            const int c4 = (t & 31) << 2;     // 0..124
            const int ks = c4 >> 3;
            const int slot = (c4 >> 2) & 1;
            #pragma unroll
            for (int it = 0; it < 8; ++it) {
                const int j  = it * 16 + r;
                const int nt = j >> 3;
                const int gg = j & 7;
                float4 wv = *(const float4*)(W + (size_t)j * CDIM + c4);
                float w[4] = {wv.x, wv.y, wv.z, wv.w};
                #pragma unroll
                for (int q = 0; q < 4; ++q) {
                    const int idx = ((nt * 16 + ks) * 32 + ((gg * 4 + q) ^ ks)) * 2 + slot;
                    uint32_t h = f2tf32(w[q]);
                    Whi[idx] = __uint_as_float(h);
                    Wlo[idx] = __uint_as_float(f2tf32(w[q] - __uint_as_float(h)));
                }
            }
        }
        __syncthreads();

        // ---- MMA mainloop: warp owns 16 m-rows x 64 j-cols (8 nt) ----
        float acc[8][4];
        #pragma unroll
        for (int nt = 0; nt < 8; ++nt)
            #pragma unroll
            for (int q = 0; q < 4; ++q) acc[nt][q] = 0.0f;

        #pragma unroll
        for (int ks = 0; ks < 16; ++ks) {
            const int c0 = tid + ks * 8;
            float ar0 = Xs[(mbase + g) * SSTR + c0];
            float ar1 = Xs[(mbase + g + 8) * SSTR + c0];
            float ar2 = Xs[(mbase + g) * SSTR + c0 + 4];
            float ar3 = Xs[(mbase + g + 8) * SSTR + c0 + 4];
            uint32_t ah0 = f2tf32(ar0), ah1 = f2tf32(ar1);
            uint32_t ah2 = f2tf32(ar2), ah3 = f2tf32(ar3);
            uint32_t al0 = f2tf32(ar0 - __uint_as_float(ah0));
            uint32_t al1 = f2tf32(ar1 - __uint_as_float(ah1));
            uint32_t al2 = f2tf32(ar2 - __uint_as_float(ah2));
            uint32_t al3 = f2tf32(ar3 - __uint_as_float(ah3));

            const int lperm = (lane ^ ks) * 2;
            #pragma unroll
            for (int nt = 0; nt < 8; ++nt) {
                const int ntg = nhalf * 8 + nt;
                const int base = (ntg * 16 + ks) * 32 * 2 + lperm;
                float2 bh = *(const float2*)(Whi + base);
                float2 bl = *(const float2*)(Wlo + base);
                uint32_t bh0 = __float_as_uint(bh.x), bh1 = __float_as_uint(bh.y);
                uint32_t bl0 = __float_as_uint(bl.x), bl1 = __float_as_uint(bl.y);
                mma_tf32(acc[nt][0], acc[nt][1], acc[nt][2], acc[nt][3],
                         ah0, ah1, ah2, ah3, bh0, bh1);
                mma_tf32(acc[nt][0], acc[nt][1], acc[nt][2], acc[nt][3],
                         al0, al1, al2, al3, bh0, bh1);
                mma_tf32(acc[nt][0], acc[nt][1], acc[nt][2], acc[nt][3],
                         ah0, ah1, ah2, ah3, bl0, bl1);
            }
        }

        __syncthreads();   // all warps done reading Whi/Wlo -> reuse as transpose buf

        // ---- Epilogue: bias + sigmoid, transpose to [j][m] via smem ----
        float* T = Whi;
        #pragma unroll
        for (int nt = 0; nt < 8; ++nt) {
            const int j0 = nhalf * 64 + nt * 8 + 2 * tid;
            const float b0v = __ldg(bias + j0);
            const float b1v = __ldg(bias + j0 + 1);
            float v0 = acc[nt][0] + b0v;
            float v1 = acc[nt][1] + b1v;
            float v2 = acc[nt][2] + b0v;
            float v3 = acc[nt][3] + b1v;
            v0 = 1.0f / (1.0f + __expf(-v0));
            v1 = 1.0f / (1.0f + __expf(-v1));
            v2 = 1.0f / (1.0f + __expf(-v2));
            v3 = 1.0f / (1.0f + __expf(-v3));
            T[j0 * SSTR + mbase + g]           = v0;
            T[(j0 + 1) * SSTR + mbase + g]     = v1;
            T[j0 * SSTR + mbase + g + 8]       = v2;
            T[(j0 + 1) * SSTR + mbase + g + 8] = v3;
        }
        __syncthreads();

        // ---- Coalesced float4 store: OutT[bidx][j][n0 + m] ----
        #pragma unroll
        for (int it = 0; it < 8; ++it) {
            const int idx = t + it * 512;       // 0..4095
            const int j   = idx >> 5;
            const int m4  = (idx & 31) << 2;
            float4 v = *(const float4*)(T + j * SSTR + m4);
            *(float4*)(OutT + ((size_t)bidx * CDIM + j) * NSEQ + n0 + m4) = v;
        }
    }
}

// ---------------------------------------------------------------------------
// Kernel 2: per-(b,c) dual-softmax attention on a [64,32] plane.
// ---------------------------------------------------------------------------
__global__ __launch_bounds__(256) void attn_kernel()
{
    const int bc = blockIdx.x;                      // b*128 + c
    const float* Qp = g_QT + (size_t)bc * NSEQ;
    const float* Kp = g_KT + (size_t)bc * NSEQ;
    const float* Vp = g_VT + (size_t)bc * NSEQ;
    float* Op = g_VT + (size_t)bc * NSEQ;           // overwrite V plane

    __shared__ float Qs[HP * WP];     // [h][w]
    __shared__ float Vs[HP * WP];     // [h][w]
    __shared__ float KTs[WP * 65];    // [w][h], padded
    __shared__ float kTs[WP * 33];    // [w][g], pooled K, padded
    __shared__ float qs[HG * WP];     // [g][w], pooled Q
    __shared__ float Kqvs[HG * WP];   // [g][w]
    __shared__ float buf[8][264];     // per-warp softmax rows

    const int t    = threadIdx.x;
    const int warp = t >> 5;
    const int lane = t & 31;

    #pragma unroll
    for (int i = 0; i < 2; ++i) {
        int idx = (t + i * 256) * 4;
        float4 qv = *(const float4*)(Qp + idx);
        float4 vv = *(const float4*)(Vp + idx);
        float4 kv = *(const float4*)(Kp + idx);
        *(float4*)(Qs + idx) = qv;
        *(float4*)(Vs + idx) = vv;
        int h = idx >> 5, w = idx & 31;
        KTs[(w + 0) * 65 + h] = kv.x;
        KTs[(w + 1) * 65 + h] = kv.y;
        KTs[(w + 2) * 65 + h] = kv.z;
        KTs[(w + 3) * 65 + h] = kv.w;
    }
    __syncthreads();

    #pragma unroll
    for (int i = 0; i < 4; ++i) {
        int idx = t + i * 256;
        int g = idx >> 5, w = idx & 31;
        qs[g * 32 + w]  = 0.5f * (Qs[(2 * g) * 32 + w] + Qs[(2 * g + 1) * 32 + w]);
        kTs[w * 33 + g] = 0.5f * (KTs[w * 65 + 2 * g] + KTs[w * 65 + 2 * g + 1]);
    }
    __syncthreads();

    // ---- Kq = softmax_h(scale * q @ K^T), Kqv = Kq @ V ----
    {
        const int g0 = warp * 4;
        float s0[4] = {0, 0, 0, 0}, s1[4] = {0, 0, 0, 0};
        #pragma unroll
        for (int w = 0; w < 32; ++w) {
            float k0 = KTs[w * 65 + lane];
            float k1 = KTs[w * 65 + 32 + lane];
            #pragma unroll
            for (int gi = 0; gi < 4; ++gi) {
                float qv = qs[(g0 + gi) * 32 + w];
                s0[gi] = fmaf(qv, k0, s0[gi]);
                s1[gi] = fmaf(qv, k1, s1[gi]);
            }
        }
        #pragma unroll
        for (int gi = 0; gi < 4; ++gi) {
            float a = s0[gi] * D_SCALE, b = s1[gi] * D_SCALE;
            float m = fmaxf(a, b);
            #pragma unroll
            for (int o = 16; o; o >>= 1) m = fmaxf(m, __shfl_xor_sync(0xffffffffu, m, o));
            float e0 = __expf(a - m), e1 = __expf(b - m);
            float sum = e0 + e1;
            #pragma unroll
            for (int o = 16; o; o >>= 1) sum += __shfl_xor_sync(0xffffffffu, sum, o);
            float r = __frcp_rn(sum);
            buf[warp][gi * 66 + lane]      = e0 * r;
            buf[warp][gi * 66 + 32 + lane] = e1 * r;
        }
        __syncwarp();
        const int gi = lane >> 3;
        const int w4 = (lane & 7) << 2;
        float4 acc = {0, 0, 0, 0};
        #pragma unroll 8
        for (int h = 0; h < 64; ++h) {
            float p  = buf[warp][gi * 66 + h];
            float4 v = *(const float4*)(Vs + h * 32 + w4);
            acc.x = fmaf(p, v.x, acc.x);
            acc.y = fmaf(p, v.y, acc.y);
            acc.z = fmaf(p, v.z, acc.z);
            acc.w = fmaf(p, v.w, acc.w);
        }
        *(float4*)(Kqvs + (g0 + gi) * 32 + w4) = acc;
    }
    __syncthreads();

    // ---- Qk = softmax_g(scale * Q @ k^T), out = Qk @ Kqv ----
    {
        const int h0 = warp * 8;
        float s[8] = {0, 0, 0, 0, 0, 0, 0, 0};
        #pragma unroll
        for (int w = 0; w < 32; ++w) {
            float kt = kTs[w * 33 + lane];
            #pragma unroll
            for (int hi = 0; hi < 8; ++hi)
                s[hi] = fmaf(Qs[(h0 + hi) * 32 + w], kt, s[hi]);
        }
        #pragma unroll
        for (int hi = 0; hi < 8; ++hi) {
            float a = s[hi] * D_SCALE;
            float m = a;
            #pragma unroll
            for (int o = 16; o; o >>= 1) m = fmaxf(m, __shfl_xor_sync(0xffffffffu, m, o));
            float e = __expf(a - m);
            float sum = e;
            #pragma unroll
            for (int o = 16; o; o >>= 1) sum += __shfl_xor_sync(0xffffffffu, sum, o);
            buf[warp][hi * 33 + lane] = e * __frcp_rn(sum);
        }
        __syncwarp();
        const int hi = lane >> 2;
        const int w8 = (lane & 3) << 3;
        float4 acc0 = {0, 0, 0, 0}, acc1 = {0, 0, 0, 0};
        #pragma unroll 8
        for (int g = 0; g < 32; ++g) {
            float p   = buf[warp][hi * 33 + g];
            float4 v0 = *(const float4*)(Kqvs + g * 32 + w8);
            float4 v1 = *(const float4*)(Kqvs + g * 32 + w8 + 4);
            acc0.x = fmaf(p, v0.x, acc0.x);
            acc0.y = fmaf(p, v0.y, acc0.y);
            acc0.z = fmaf(p, v0.z, acc0.z);
            acc0.w = fmaf(p, v0.w, acc0.w);
            acc1.x = fmaf(p, v1.x, acc1.x);
            acc1.y = fmaf(p, v1.y, acc1.y);
            acc1.z = fmaf(p, v1.z, acc1.z);
            acc1.w = fmaf(p, v1.w, acc1.w);
        }
        float* dst = Op + (h0 + hi) * 32 + w8;
        *(float4*)(dst)     = acc0;
        *(float4*)(dst + 4) = acc1;
    }
}

// ---------------------------------------------------------------------------
// Kernel 3: [B, C, N] -> [B, N, C] transpose (output epilogue).
// ---------------------------------------------------------------------------
__global__ __launch_bounds__(256) void transpose_kernel(float* __restrict__ out)
{
    __shared__ float tile[32][33];
    const int b  = blockIdx.z;
    const int c0 = blockIdx.y * 32;
    const int n0 = blockIdx.x * 32;
    const int tx = threadIdx.x;
    const int ty = threadIdx.y;

    const float* src = g_VT + (size_t)b * CDIM * NSEQ;
    #pragma unroll
    for (int i = 0; i < 32; i += 8)
        tile[ty + i][tx] = src[(size_t)(c0 + ty + i) * NSEQ + n0 + tx];
    __syncthreads();
    #pragma unroll
    for (int i = 0; i < 32; i += 8)
        out[((size_t)b * NSEQ + n0 + ty + i) * CDIM + c0 + tx] = tile[tx][ty + i];
}

// ---------------------------------------------------------------------------
extern "C" void kernel_launch(void* const* d_in, const int* in_sizes, int n_in,
                              void* d_out, int out_size)
{
    (void)in_sizes; (void)n_in; (void)out_size;
    const float* X  = (const float*)d_in[0];
    const float* Wq = (const float*)d_in[1];
    const float* bq = (const float*)d_in[2];
    const float* Wk = (const float*)d_in[3];
    const float* bk = (const float*)d_in[4];
    const float* Wv = (const float*)d_in[5];
    const float* bv = (const float*)d_in[6];
    float* out = (float*)d_out;

    // Xs 128*SSTR + Wpk hi/lo 2*16384 floats
    const size_t proj_smem = ((size_t)128 * SSTR + 2 * 16 * 16 * 32 * 2) * sizeof(float);
    cudaFuncSetAttribute(proj_mma_kernel, cudaFuncAttributeMaxDynamicSharedMemorySize,
                         (int)proj_smem);

    proj_mma_kernel<<<dim3(1024, 1, 1), 512, proj_smem>>>(X, Wq, bq, Wk, bk, Wv, bv);
    attn_kernel<<<dim3(BATCH * CDIM, 1, 1), 256>>>();
    transpose_kernel<<<dim3(NSEQ / 32, CDIM / 32, BATCH), dim3(32, 8, 1)>>>(out);
}

// round 4
// speedup vs baseline: 1.5554x; 1.1202x over previous
#include <cuda_runtime.h>
#include <cstdint>

#define BATCH 64
#define NSEQ  2048
#define CDIM  128
#define HP    64
#define WP    32
#define HG    32   // HP / POOL
#define D_SCALE 0.08838834764831845f  // 1/sqrt(128)

// Scratch: Q,K,V in [B, C, N] (spatial-major) layout. V plane is overwritten
// with the attention output by attn_kernel (each CTA exclusively owns its plane,
// and proj writes it fully on every graph replay -> deterministic).
__device__ float g_QT[(size_t)BATCH * CDIM * NSEQ];
__device__ float g_KT[(size_t)BATCH * CDIM * NSEQ];
__device__ float g_VT[(size_t)BATCH * CDIM * NSEQ];

#define SSTR 132   // smem row stride (floats) for X / transpose buffer

// Pack two fp32 into bf16x2: e0 -> low 16 bits (even k), e1 -> high (odd k).
__device__ __forceinline__ uint32_t bf16x2_of(float e0, float e1) {
    uint32_t r;
    asm("cvt.rn.bf16x2.f32 %0, %1, %2;" : "=r"(r) : "f"(e1), "f"(e0));
    return r;
}
__device__ __forceinline__ float lo_f(uint32_t p) { return __uint_as_float(p << 16); }
__device__ __forceinline__ float hi_f(uint32_t p) { return __uint_as_float(p & 0xffff0000u); }

__device__ __forceinline__ void mma_bf16(float& d0, float& d1, float& d2, float& d3,
                                         uint32_t a0, uint32_t a1, uint32_t a2, uint32_t a3,
                                         uint32_t b0, uint32_t b1) {
    asm volatile(
        "mma.sync.aligned.m16n8k16.row.col.f32.bf16.bf16.f32 "
        "{%0,%1,%2,%3}, {%4,%5,%6,%7}, {%8,%9}, {%0,%1,%2,%3};"
        : "+f"(d0), "+f"(d1), "+f"(d2), "+f"(d3)
        : "r"(a0), "r"(a1), "r"(a2), "r"(a3), "r"(b0), "r"(b1));
}

// ---------------------------------------------------------------------------
// Kernel 1: projection GEMMs on tensor cores, 3-term bf16 split
// (aHi*bHi + aLo*bHi + aHi*bLo; dropped lo*lo ~2^-18 relative).
// 512 threads = 16 warps: warp = (mgroup 0..7) x (nhalf 0..1).
// W staged in smem fragment-packed: uint4 = (bh0, bh1, bl0, bl1) per (nt,ks,lane)
// -> one LDS.128 feeds 3 MMAs.
// Out[m,j] = sigmoid(sum_c X[m,c] W[j,c] + b[j]), stored transposed OutT[b][j][n].
// ---------------------------------------------------------------------------
__global__ __launch_bounds__(512) void proj_mma_kernel(
    const float* __restrict__ X,
    const float* __restrict__ Wq, const float* __restrict__ bq,
    const float* __restrict__ Wk, const float* __restrict__ bk,
    const float* __restrict__ Wv, const float* __restrict__ bv)
{
    extern __shared__ float sm[];
    float* Xs  = sm;                        // [m][c] 128 x SSTR fp32 (67.6 KB)
    uint4* Wpk = (uint4*)(sm + 128 * SSTR); // [16 nt][8 ks][32 lane] uint4 (64 KB)
    // epilogue transpose buffer T reuses the Wpk region (67.6 KB allocated)

    const int t    = threadIdx.x;
    const int warp = t >> 5;
    const int lane = t & 31;
    const int M0   = blockIdx.x * 128;
    const int bidx = M0 >> 11;          // batch index (128 | 2048)
    const int n0   = M0 & 2047;         // seq offset within batch

    // ---- Stage X tile [128 x 128] fp32 ----
    {
        const int r  = t >> 5;           // 0..15
        const int c4 = (t & 31) << 2;    // 0..124
        #pragma unroll
        for (int it = 0; it < 8; ++it) {
            const int row = it * 16 + r;
            float4 xv = *(const float4*)(X + (size_t)(M0 + row) * CDIM + c4);
            *(float4*)(Xs + row * SSTR + c4) = xv;
        }
    }

    const int g      = lane >> 2;    // 0..7
    const int tid    = lane & 3;     // 0..3
    const int mgroup = warp & 7;
    const int nhalf  = warp >> 3;
    const int mbase  = mgroup * 16;

    #pragma unroll 1
    for (int p = 0; p < 3; ++p) {
        const float* W    = (p == 0) ? Wq : (p == 1) ? Wk : Wv;
        const float* bias = (p == 0) ? bq : (p == 1) ? bk : bv;
        float* OutT       = (p == 0) ? g_QT : (p == 1) ? g_KT : g_VT;

        __syncthreads();   // prev epilogue done with Wpk region; Xs stable

        // ---- Stage W fragment-packed bf16 hi/lo ----
        // W[j][c]: nt=j>>3, gj=j&7, ks=c>>4, kk=c&15.
        // word: kk<8 -> (b0: .x hi, .z lo), kk>=8 -> (b1: .y hi, .w lo)
        // lane slot = gj*4 + ((kk&7)>>1); bit pos: kk&1 (0=low16).
        {
            const int r      = t >> 5;          // 0..15 (j group)
            const int c4     = (t & 31) << 2;   // 0..124
            const int ks     = c4 >> 4;
            const int hiword = ((c4 & 15) >= 8) ? 1 : 0;
            const int tidA   = (c4 & 7) >> 1;   // 0 or 2
            #pragma unroll
            for (int it = 0; it < 8; ++it) {
                const int j  = it * 16 + r;
                const int nt = j >> 3;
                const int gj = j & 7;
                float4 wv = *(const float4*)(W + (size_t)j * CDIM + c4);
                uint32_t hiA = bf16x2_of(wv.x, wv.y);
                uint32_t hiB = bf16x2_of(wv.z, wv.w);
                uint32_t loA = bf16x2_of(wv.x - lo_f(hiA), wv.y - hi_f(hiA));
                uint32_t loB = bf16x2_of(wv.z - lo_f(hiB), wv.w - hi_f(hiB));
                uint32_t* dst = (uint32_t*)(Wpk + ((nt * 8 + ks) * 32 + gj * 4 + tidA));
                dst[hiword]         = hiA;
                dst[hiword + 2]     = loA;
                dst[4 + hiword]     = hiB;
                dst[4 + hiword + 2] = loB;
            }
        }
        __syncthreads();

        // ---- MMA mainloop: warp owns 16 m-rows x 64 j-cols (8 nt) ----
        float acc[8][4];
        #pragma unroll
        for (int nt = 0; nt < 8; ++nt)
            #pragma unroll
            for (int q = 0; q < 4; ++q) acc[nt][q] = 0.0f;

        #pragma unroll
        for (int ks = 0; ks < 8; ++ks) {
            const int c0 = ks * 16 + 2 * tid;
            const float* xr0 = Xs + (mbase + g) * SSTR + c0;
            const float* xr1 = Xs + (mbase + g + 8) * SSTR + c0;
            float2 x00 = *(const float2*)(xr0);
            float2 x02 = *(const float2*)(xr0 + 8);
            float2 x10 = *(const float2*)(xr1);
            float2 x12 = *(const float2*)(xr1 + 8);
            uint32_t ah0 = bf16x2_of(x00.x, x00.y);
            uint32_t ah1 = bf16x2_of(x10.x, x10.y);
            uint32_t ah2 = bf16x2_of(x02.x, x02.y);
            uint32_t ah3 = bf16x2_of(x12.x, x12.y);
            uint32_t al0 = bf16x2_of(x00.x - lo_f(ah0), x00.y - hi_f(ah0));
            uint32_t al1 = bf16x2_of(x10.x - lo_f(ah1), x10.y - hi_f(ah1));
            uint32_t al2 = bf16x2_of(x02.x - lo_f(ah2), x02.y - hi_f(ah2));
            uint32_t al3 = bf16x2_of(x12.x - lo_f(ah3), x12.y - hi_f(ah3));

            #pragma unroll
            for (int nt = 0; nt < 8; ++nt) {
                const int ntg = nhalf * 8 + nt;
                uint4 w = Wpk[(ntg * 8 + ks) * 32 + lane];
                mma_bf16(acc[nt][0], acc[nt][1], acc[nt][2], acc[nt][3],
                         ah0, ah1, ah2, ah3, w.x, w.y);
                mma_bf16(acc[nt][0], acc[nt][1], acc[nt][2], acc[nt][3],
                         al0, al1, al2, al3, w.x, w.y);
                mma_bf16(acc[nt][0], acc[nt][1], acc[nt][2], acc[nt][3],
                         ah0, ah1, ah2, ah3, w.z, w.w);
            }
        }

        __syncthreads();   // all warps done reading Wpk -> reuse as transpose buf

        // ---- Epilogue: bias + sigmoid, transpose to [j][m] via smem ----
        float* T = (float*)Wpk;
        #pragma unroll
        for (int nt = 0; nt < 8; ++nt) {
            const int j0 = nhalf * 64 + nt * 8 + 2 * tid;
            const float b0v = __ldg(bias + j0);
            const float b1v = __ldg(bias + j0 + 1);
            float v0 = acc[nt][0] + b0v;
            float v1 = acc[nt][1] + b1v;
            float v2 = acc[nt][2] + b0v;
            float v3 = acc[nt][3] + b1v;
            v0 = 1.0f / (1.0f + __expf(-v0));
            v1 = 1.0f / (1.0f + __expf(-v1));
            v2 = 1.0f / (1.0f + __expf(-v2));
            v3 = 1.0f / (1.0f + __expf(-v3));
            T[j0 * SSTR + mbase + g]           = v0;
            T[(j0 + 1) * SSTR + mbase + g]     = v1;
            T[j0 * SSTR + mbase + g + 8]       = v2;
            T[(j0 + 1) * SSTR + mbase + g + 8] = v3;
        }
        __syncthreads();

        // ---- Coalesced float4 store: OutT[bidx][j][n0 + m] ----
        #pragma unroll
        for (int it = 0; it < 8; ++it) {
            const int idx = t + it * 512;       // 0..4095
            const int j   = idx >> 5;
            const int m4  = (idx & 31) << 2;
            float4 v = *(const float4*)(T + j * SSTR + m4);
            *(float4*)(OutT + ((size_t)bidx * CDIM + j) * NSEQ + n0 + m4) = v;
        }
    }
}

// ---------------------------------------------------------------------------
// Kernel 2: per-(b,c) dual-softmax attention on a [64,32] plane.
// ---------------------------------------------------------------------------
__global__ __launch_bounds__(256) void attn_kernel()
{
    const int bc = blockIdx.x;                      // b*128 + c
    const float* Qp = g_QT + (size_t)bc * NSEQ;
    const float* Kp = g_KT + (size_t)bc * NSEQ;
    const float* Vp = g_VT + (size_t)bc * NSEQ;
    float* Op = g_VT + (size_t)bc * NSEQ;           // overwrite V plane

    __shared__ float Qs[HP * WP];     // [h][w]
    __shared__ float Vs[HP * WP];     // [h][w]
    __shared__ float KTs[WP * 65];    // [w][h], padded
    __shared__ float kTs[WP * 33];    // [w][g], pooled K, padded
    __shared__ float qs[HG * WP];     // [g][w], pooled Q
    __shared__ float Kqvs[HG * WP];   // [g][w]
    __shared__ float buf[8][264];     // per-warp softmax rows

    const int t    = threadIdx.x;
    const int warp = t >> 5;
    const int lane = t & 31;

    #pragma unroll
    for (int i = 0; i < 2; ++i) {
        int idx = (t + i * 256) * 4;
        float4 qv = *(const float4*)(Qp + idx);
        float4 vv = *(const float4*)(Vp + idx);
        float4 kv = *(const float4*)(Kp + idx);
        *(float4*)(Qs + idx) = qv;
        *(float4*)(Vs + idx) = vv;
        int h = idx >> 5, w = idx & 31;
        KTs[(w + 0) * 65 + h] = kv.x;
        KTs[(w + 1) * 65 + h] = kv.y;
        KTs[(w + 2) * 65 + h] = kv.z;
        KTs[(w + 3) * 65 + h] = kv.w;
    }
    __syncthreads();

    #pragma unroll
    for (int i = 0; i < 4; ++i) {
        int idx = t + i * 256;
        int g = idx >> 5, w = idx & 31;
        qs[g * 32 + w]  = 0.5f * (Qs[(2 * g) * 32 + w] + Qs[(2 * g + 1) * 32 + w]);
        kTs[w * 33 + g] = 0.5f * (KTs[w * 65 + 2 * g] + KTs[w * 65 + 2 * g + 1]);
    }
    __syncthreads();

    // ---- Kq = softmax_h(scale * q @ K^T), Kqv = Kq @ V ----
    {
        const int g0 = warp * 4;
        float s0[4] = {0, 0, 0, 0}, s1[4] = {0, 0, 0, 0};
        #pragma unroll
        for (int w = 0; w < 32; ++w) {
            float k0 = KTs[w * 65 + lane];
            float k1 = KTs[w * 65 + 32 + lane];
            #pragma unroll
            for (int gi = 0; gi < 4; ++gi) {
                float qv = qs[(g0 + gi) * 32 + w];
                s0[gi] = fmaf(qv, k0, s0[gi]);
                s1[gi] = fmaf(qv, k1, s1[gi]);
            }
        }
        #pragma unroll
        for (int gi = 0; gi < 4; ++gi) {
            float a = s0[gi] * D_SCALE, b = s1[gi] * D_SCALE;
            float m = fmaxf(a, b);
            #pragma unroll
            for (int o = 16; o; o >>= 1) m = fmaxf(m, __shfl_xor_sync(0xffffffffu, m, o));
            float e0 = __expf(a - m), e1 = __expf(b - m);
            float sum = e0 + e1;
            #pragma unroll
            for (int o = 16; o; o >>= 1) sum += __shfl_xor_sync(0xffffffffu, sum, o);
            float r = __frcp_rn(sum);
            buf[warp][gi * 66 + lane]      = e0 * r;
            buf[warp][gi * 66 + 32 + lane] = e1 * r;
        }
        __syncwarp();
        const int gi = lane >> 3;
        const int w4 = (lane & 7) << 2;
        float4 acc = {0, 0, 0, 0};
        #pragma unroll 8
        for (int h = 0; h < 64; ++h) {
            float p  = buf[warp][gi * 66 + h];
            float4 v = *(const float4*)(Vs + h * 32 + w4);
            acc.x = fmaf(p, v.x, acc.x);
            acc.y = fmaf(p, v.y, acc.y);
            acc.z = fmaf(p, v.z, acc.z);
            acc.w = fmaf(p, v.w, acc.w);
        }
        *(float4*)(Kqvs + (g0 + gi) * 32 + w4) = acc;
    }
    __syncthreads();

    // ---- Qk = softmax_g(scale * Q @ k^T), out = Qk @ Kqv ----
    {
        const int h0 = warp * 8;
        float s[8] = {0, 0, 0, 0, 0, 0, 0, 0};
        #pragma unroll
        for (int w = 0; w < 32; ++w) {
            float kt = kTs[w * 33 + lane];
            #pragma unroll
            for (int hi = 0; hi < 8; ++hi)
                s[hi] = fmaf(Qs[(h0 + hi) * 32 + w], kt, s[hi]);
        }
        #pragma unroll
        for (int hi = 0; hi < 8; ++hi) {
            float a = s[hi] * D_SCALE;
            float m = a;
            #pragma unroll
            for (int o = 16; o; o >>= 1) m = fmaxf(m, __shfl_xor_sync(0xffffffffu, m, o));
            float e = __expf(a - m);
            float sum = e;
            #pragma unroll
            for (int o = 16; o; o >>= 1) sum += __shfl_xor_sync(0xffffffffu, sum, o);
            buf[warp][hi * 33 + lane] = e * __frcp_rn(sum);
        }
        __syncwarp();
        const int hi = lane >> 2;
        const int w8 = (lane & 3) << 3;
        float4 acc0 = {0, 0, 0, 0}, acc1 = {0, 0, 0, 0};
        #pragma unroll 8
        for (int g = 0; g < 32; ++g) {
            float p   = buf[warp][hi * 33 + g];
            float4 v0 = *(const float4*)(Kqvs + g * 32 + w8);
            float4 v1 = *(const float4*)(Kqvs + g * 32 + w8 + 4);
            acc0.x = fmaf(p, v0.x, acc0.x);
            acc0.y = fmaf(p, v0.y, acc0.y);
            acc0.z = fmaf(p, v0.z, acc0.z);
            acc0.w = fmaf(p, v0.w, acc0.w);
            acc1.x = fmaf(p, v1.x, acc1.x);
            acc1.y = fmaf(p, v1.y, acc1.y);
            acc1.z = fmaf(p, v1.z, acc1.z);
            acc1.w = fmaf(p, v1.w, acc1.w);
        }
        float* dst = Op + (h0 + hi) * 32 + w8;
        *(float4*)(dst)     = acc0;
        *(float4*)(dst + 4) = acc1;
    }
}

// ---------------------------------------------------------------------------
// Kernel 3: [B, C, N] -> [B, N, C] transpose (output epilogue).
// ---------------------------------------------------------------------------
__global__ __launch_bounds__(256) void transpose_kernel(float* __restrict__ out)
{
    __shared__ float tile[32][33];
    const int b  = blockIdx.z;
    const int c0 = blockIdx.y * 32;
    const int n0 = blockIdx.x * 32;
    const int tx = threadIdx.x;
    const int ty = threadIdx.y;

    const float* src = g_VT + (size_t)b * CDIM * NSEQ;
    #pragma unroll
    for (int i = 0; i < 32; i += 8)
        tile[ty + i][tx] = src[(size_t)(c0 + ty + i) * NSEQ + n0 + tx];
    __syncthreads();
    #pragma unroll
    for (int i = 0; i < 32; i += 8)
        out[((size_t)b * NSEQ + n0 + ty + i) * CDIM + c0 + tx] = tile[tx][ty + i];
}

// ---------------------------------------------------------------------------
extern "C" void kernel_launch(void* const* d_in, const int* in_sizes, int n_in,
                              void* d_out, int out_size)
{
    (void)in_sizes; (void)n_in; (void)out_size;
    const float* X  = (const float*)d_in[0];
    const float* Wq = (const float*)d_in[1];
    const float* bq = (const float*)d_in[2];
    const float* Wk = (const float*)d_in[3];
    const float* bk = (const float*)d_in[4];
    const float* Wv = (const float*)d_in[5];
    const float* bv = (const float*)d_in[6];
    float* out = (float*)d_out;

    // Xs (128*SSTR) + max(Wpk 16384 floats, T 128*SSTR floats) = 2*128*SSTR
    const size_t proj_smem = (size_t)2 * 128 * SSTR * sizeof(float);  // 135168 B
    cudaFuncSetAttribute(proj_mma_kernel, cudaFuncAttributeMaxDynamicSharedMemorySize,
                         (int)proj_smem);

    proj_mma_kernel<<<dim3(1024, 1, 1), 512, proj_smem>>>(X, Wq, bq, Wk, bk, Wv, bv);
    attn_kernel<<<dim3(BATCH * CDIM, 1, 1), 256>>>();
    transpose_kernel<<<dim3(NSEQ / 32, CDIM / 32, BATCH), dim3(32, 8, 1)>>>(out);
}